// round 13
// baseline (speedup 1.0000x reference)
#include <cuda_runtime.h>
#include <cuda_bf16.h>
#include <cuda_fp16.h>
#include <cstdint>

#define NN 50000
#define NE 640000
#define D  128
#define NG 512
#define NBLK ((NN + 255) / 256)
#define NTILE ((NN + 127) / 128)
#define GR_SPMM ((NN * 32 + 255) / 256)

// dynamic smem layout for k_gemm (bytes)
#define A_HI_OFF 0        // [2][128][40] bf16 : 2*10240
#define A_LO_OFF 20480
#define B_HI_OFF 40960    // [2][32][136] bf16 : 2*8704
#define B_LO_OFF 58368
#define SB_OFF   75776    // float[128]
#define GEMM_SMEM 76288
#define ABUF 10240
#define BBUF 8704

// ---------------- scratch (static device globals) --------------------------
__device__ __align__(16) float g_h[NN * D];
__device__ __align__(16) __half g_hf[NN * D];      // fp16 mirror (gather source)
__device__ __align__(16) float g_u32[NN * D];
__device__ __align__(16) __nv_bfloat16 g_uhi[NN * D];
__device__ __align__(16) __nv_bfloat16 g_ulo[NN * D];
__device__ __align__(16) __nv_bfloat16 g_vhi[NN * D];
__device__ __align__(16) __nv_bfloat16 g_vlo[NN * D];
__device__ __align__(16) __nv_bfloat16 g_Whi[4 * 256 * 128];
__device__ __align__(16) __nv_bfloat16 g_Wlo[4 * 256 * 128];
__device__ __align__(16) float g_Wcomb[256 * 128];
__device__ float g_bw[128];
__device__ float g_t0[128];
__device__ float g_invdeg[NN];
__device__ float g_c[NN];
__device__ int   g_indeg[NN];      // zero-initialized; re-zeroed by k_scan3z
__device__ int   g_rowptr[NN + 1];
__device__ int   g_fill[NN];
__device__ int   g_bsum[NBLK + 32];
__device__ __align__(8) int2 g_csr[NE];     // (src, eid)

// ---------------- helpers ---------------------------------------------------
__device__ __forceinline__ unsigned short bf_bits(__nv_bfloat16 h) {
    unsigned short u; memcpy(&u, &h, 2); return u;
}
__device__ __forceinline__ void split4(float4 a, uint2& hi, uint2& lo) {
    __nv_bfloat16 h0 = __float2bfloat16(a.x), h1 = __float2bfloat16(a.y);
    __nv_bfloat16 h2 = __float2bfloat16(a.z), h3 = __float2bfloat16(a.w);
    __nv_bfloat16 l0 = __float2bfloat16(a.x - __bfloat162float(h0));
    __nv_bfloat16 l1 = __float2bfloat16(a.y - __bfloat162float(h1));
    __nv_bfloat16 l2 = __float2bfloat16(a.z - __bfloat162float(h2));
    __nv_bfloat16 l3 = __float2bfloat16(a.w - __bfloat162float(h3));
    hi.x = (unsigned)bf_bits(h0) | ((unsigned)bf_bits(h1) << 16);
    hi.y = (unsigned)bf_bits(h2) | ((unsigned)bf_bits(h3) << 16);
    lo.x = (unsigned)bf_bits(l0) | ((unsigned)bf_bits(l1) << 16);
    lo.y = (unsigned)bf_bits(l2) | ((unsigned)bf_bits(l3) << 16);
}
__device__ __forceinline__ void addh8(float* acc, uint4 v) {
    float2 f;
    f = __half22float2(*(__half2*)&v.x); acc[0] += f.x; acc[1] += f.y;
    f = __half22float2(*(__half2*)&v.y); acc[2] += f.x; acc[3] += f.y;
    f = __half22float2(*(__half2*)&v.z); acc[4] += f.x; acc[5] += f.y;
    f = __half22float2(*(__half2*)&v.w); acc[6] += f.x; acc[7] += f.y;
}
__device__ __forceinline__ uint32_t sptr(const void* p) {
    return (uint32_t)__cvta_generic_to_shared(p);
}

#define LDSM4(R, addr) \
    asm volatile("ldmatrix.sync.aligned.m8n8.x4.shared.b16 {%0,%1,%2,%3},[%4];" \
        : "=r"((R)[0]), "=r"((R)[1]), "=r"((R)[2]), "=r"((R)[3]) : "r"(addr))
#define LDSM4T(R, addr) \
    asm volatile("ldmatrix.sync.aligned.m8n8.x4.trans.shared.b16 {%0,%1,%2,%3},[%4];" \
        : "=r"((R)[0]), "=r"((R)[1]), "=r"((R)[2]), "=r"((R)[3]) : "r"(addr))
#define MMA(C, A, B) \
    asm volatile("mma.sync.aligned.m16n8k16.row.col.f32.bf16.bf16.f32 " \
        "{%0,%1,%2,%3},{%4,%5,%6,%7},{%8,%9},{%0,%1,%2,%3};" \
        : "+f"((C)[0]), "+f"((C)[1]), "+f"((C)[2]), "+f"((C)[3]) \
        : "r"((A)[0]), "r"((A)[1]), "r"((A)[2]), "r"((A)[3]), "r"((B)[0]), "r"((B)[1]))
#define CP16(dst, src) \
    asm volatile("cp.async.cg.shared.global [%0], [%1], 16;" :: "r"(dst), "l"(src))
#define CPCOMMIT() asm volatile("cp.async.commit_group;")
#define CPWAIT(n)  asm volatile("cp.async.wait_group %0;" :: "n"(n))

// ---------------- CSR build -------------------------------------------------
__global__ void k_count(const int* __restrict__ ei) {
    int e = blockIdx.x * blockDim.x + threadIdx.x;
    if (e < NE) atomicAdd(&g_indeg[ei[NE + e]], 1);
}
__global__ void k_scan1() {
    __shared__ int sm[8];
    int t = threadIdx.x, lane = t & 31, wid = t >> 5;
    int i = blockIdx.x * 256 + t;
    int v = (i < NN) ? g_indeg[i] : 0;
#pragma unroll
    for (int s = 16; s > 0; s >>= 1) v += __shfl_down_sync(0xffffffffu, v, s);
    if (lane == 0) sm[wid] = v;
    __syncthreads();
    if (t == 0) {
        int s = 0;
#pragma unroll
        for (int w = 0; w < 8; w++) s += sm[w];
        g_bsum[blockIdx.x] = s;
    }
}
__global__ void k_scan3z() {
    __shared__ int red[8];
    __shared__ int ws[8];
    __shared__ int s_base, s_tot;
    int t = threadIdx.x, lane = t & 31, wid = t >> 5;
    int part = 0;
    for (int j = t; j < blockIdx.x; j += 256) part += g_bsum[j];
#pragma unroll
    for (int s = 16; s > 0; s >>= 1) part += __shfl_down_sync(0xffffffffu, part, s);
    if (lane == 0) red[wid] = part;
    __syncthreads();
    if (t == 0) {
        int b = 0;
#pragma unroll
        for (int w = 0; w < 8; w++) b += red[w];
        s_base = b;
    }
    int i = blockIdx.x * 256 + t;
    int v = (i < NN) ? g_indeg[i] : 0;
    int x = v;
#pragma unroll
    for (int s = 1; s < 32; s <<= 1) {
        int tt = __shfl_up_sync(0xffffffffu, x, s);
        if (lane >= s) x += tt;
    }
    if (lane == 31) ws[wid] = x;
    __syncthreads();
    if (t == 0) {
        int acc = 0;
#pragma unroll
        for (int w = 0; w < 8; w++) { int tmp = ws[w]; ws[w] = acc; acc += tmp; }
        s_tot = acc;
    }
    __syncthreads();
    if (i < NN) {
        g_rowptr[i] = s_base + ws[wid] + x - v;
        g_invdeg[i] = 1.0f / fmaxf((float)v, 1.0f);
        g_c[i] = (v > 0) ? 2.0f : 1.0f;
        g_fill[i] = 0;
        g_indeg[i] = 0;
    }
    if (blockIdx.x == NBLK - 1 && t == 0) g_rowptr[NN] = s_base + s_tot;
}
__global__ void k_fill(const int* __restrict__ ei) {
    int e = blockIdx.x * blockDim.x + threadIdx.x;
    if (e < NE) {
        int dst = ei[NE + e];
        int p = g_rowptr[dst] + atomicAdd(&g_fill[dst], 1);
        g_csr[p] = make_int2(ei[e], e);
    }
}

// merged weight prep
__global__ void k_prep(const float* __restrict__ Ws, const float* __restrict__ Wes,
                       const float* __restrict__ bs, const float* __restrict__ Wp,
                       const float* __restrict__ emb) {
    int b = blockIdx.x;
    if (b < 512) {
        int i = b * 256 + threadIdx.x;
        int l = i >> 15, rem = i & 32767;
        int k = rem >> 7, n = rem & 127;
        float v = (k < 128) ? Ws[l * 16384 + k * 128 + n]
                            : Wes[l * 16384 + (k - 128) * 128 + n];
        __nv_bfloat16 h = __float2bfloat16(v);
        g_Whi[i] = h;
        g_Wlo[i] = __float2bfloat16(v - __bfloat162float(h));
    } else if (b == 512) {
        int t = threadIdx.x;
        if (t < 128) {
            float acc = bs[t];
#pragma unroll 8
            for (int k = 0; k < 128; k++) acc = fmaf(emb[k], Ws[k * 128 + t], acc);
            g_t0[t] = acc;
        }
    } else if (b == 513) {
        int t = threadIdx.x;
        if (t < 128) {
            float acc = 0.f;
#pragma unroll 8
            for (int k = 0; k < 128; k++) acc = fmaf(bs[4 * 128 + k], Wp[k * 128 + t], acc);
            g_bw[t] = acc;
        }
    } else {
        int i = (b - 514) * 256 + threadIdx.x;
        int r = i >> 7, c = i & 127;
        const float* Wrow = (r < 128) ? (Ws + 4 * 16384 + r * 128)
                                      : (Wes + 4 * 16384 + (r - 128) * 128);
        float acc = 0.f;
#pragma unroll 8
        for (int k = 0; k < 128; k++) acc = fmaf(Wrow[k], Wp[k * 128 + c], acc);
        g_Wcomb[i] = acc;
    }
}

// V[i] = (sum edge_attr)/deg -> split bf16 (fp32 input; unchanged)
__global__ void k_v(const float* __restrict__ ea) {
    int gt = blockIdx.x * blockDim.x + threadIdx.x;
    int w = gt >> 5, lane = gt & 31;
    if (w >= NN) return;
    int s = g_rowptr[w], t = g_rowptr[w + 1];
    float4 acc = make_float4(0.f, 0.f, 0.f, 0.f);
    const float4* ea4 = (const float4*)ea;
    int p = s;
    for (; p + 1 < t; p += 2) {
        int2 c0 = g_csr[p], c1 = g_csr[p + 1];
        float4 x0 = ea4[c0.y * 32 + lane];
        float4 x1 = ea4[c1.y * 32 + lane];
        acc.x += x0.x + x1.x; acc.y += x0.y + x1.y;
        acc.z += x0.z + x1.z; acc.w += x0.w + x1.w;
    }
    if (p < t) {
        float4 x0 = ea4[g_csr[p].y * 32 + lane];
        acc.x += x0.x; acc.y += x0.y; acc.z += x0.z; acc.w += x0.w;
    }
    float id = g_invdeg[w];
    acc.x *= id; acc.y *= id; acc.z *= id; acc.w *= id;
    uint2 hi, lo; split4(acc, hi, lo);
    ((uint2*)g_vhi)[w * 32 + lane] = hi;
    ((uint2*)g_vlo)[w * 32 + lane] = lo;
}

// u = h + (sum hf[src])/deg -> split bf16.
// fp16 gather: 16 lanes per edge (row = 16 x 16B), 2 edges per warp-iteration.
__global__ void k_spmm_split() {
    int gt = blockIdx.x * blockDim.x + threadIdx.x;
    int w = gt >> 5, lane = gt & 31;
    if (w >= NN) return;
    int s = g_rowptr[w], t = g_rowptr[w + 1];
    int half = lane >> 4, sub = lane & 15;
    float acc[8];
#pragma unroll
    for (int i = 0; i < 8; i++) acc[i] = 0.f;
    const uint4* hf = (const uint4*)g_hf;    // 16 uint4 per row
    int p = s + half;
    for (; p + 2 < t; p += 4) {
        int s0 = g_csr[p].x, s1 = g_csr[p + 2].x;
        uint4 x0 = hf[s0 * 16 + sub];
        uint4 x1 = hf[s1 * 16 + sub];
        addh8(acc, x0);
        addh8(acc, x1);
    }
    if (p < t) {
        uint4 x0 = hf[g_csr[p].x * 16 + sub];
        addh8(acc, x0);
    }
#pragma unroll
    for (int i = 0; i < 8; i++) acc[i] += __shfl_xor_sync(0xffffffffu, acc[i], 16);
    if (half == 0) {
        float id = g_invdeg[w];
        const float4* h4 = (const float4*)g_h;
        float4 h0 = h4[w * 32 + sub * 2];
        float4 h1 = h4[w * 32 + sub * 2 + 1];
        float4 r0 = make_float4(h0.x + acc[0] * id, h0.y + acc[1] * id,
                                h0.z + acc[2] * id, h0.w + acc[3] * id);
        float4 r1 = make_float4(h1.x + acc[4] * id, h1.y + acc[5] * id,
                                h1.z + acc[6] * id, h1.w + acc[7] * id);
        uint2 hi0, lo0, hi1, lo1;
        split4(r0, hi0, lo0);
        split4(r1, hi1, lo1);
        *(uint4*)(g_uhi + w * 128 + sub * 8) = make_uint4(hi0.x, hi0.y, hi1.x, hi1.y);
        *(uint4*)(g_ulo + w * 128 + sub * 8) = make_uint4(lo0.x, lo0.y, lo1.x, lo1.y);
    }
}

// u (layer 4) -> fp32 for pooled path; same fp16 gather scheme
__global__ void k_spmm_f32() {
    int gt = blockIdx.x * blockDim.x + threadIdx.x;
    int w = gt >> 5, lane = gt & 31;
    if (w >= NN) return;
    int s = g_rowptr[w], t = g_rowptr[w + 1];
    int half = lane >> 4, sub = lane & 15;
    float acc[8];
#pragma unroll
    for (int i = 0; i < 8; i++) acc[i] = 0.f;
    const uint4* hf = (const uint4*)g_hf;
    int p = s + half;
    for (; p + 2 < t; p += 4) {
        int s0 = g_csr[p].x, s1 = g_csr[p + 2].x;
        uint4 x0 = hf[s0 * 16 + sub];
        uint4 x1 = hf[s1 * 16 + sub];
        addh8(acc, x0);
        addh8(acc, x1);
    }
    if (p < t) {
        uint4 x0 = hf[g_csr[p].x * 16 + sub];
        addh8(acc, x0);
    }
#pragma unroll
    for (int i = 0; i < 8; i++) acc[i] += __shfl_xor_sync(0xffffffffu, acc[i], 16);
    if (half == 0) {
        float id = g_invdeg[w];
        const float4* h4 = (const float4*)g_h;
        float4 h0 = h4[w * 32 + sub * 2];
        float4 h1 = h4[w * 32 + sub * 2 + 1];
        float4 r0 = make_float4(h0.x + acc[0] * id, h0.y + acc[1] * id,
                                h0.z + acc[2] * id, h0.w + acc[3] * id);
        float4 r1 = make_float4(h1.x + acc[4] * id, h1.y + acc[5] * id,
                                h1.z + acc[6] * id, h1.w + acc[7] * id);
        ((float4*)g_u32)[w * 32 + sub * 2] = r0;
        ((float4*)g_u32)[w * 32 + sub * 2 + 1] = r1;
    }
}

// g_h (+fp16 mirror) = relu( [u|v] @ [W;We] + c*t ) — bf16x3 mma, cp.async.
__global__ __launch_bounds__(256, 2) void k_gemm(int layer, int first_stage,
                                                 const float* __restrict__ tvec) {
    extern __shared__ char sm_[];
    __nv_bfloat16* As_hi = (__nv_bfloat16*)(sm_ + A_HI_OFF);
    __nv_bfloat16* As_lo = (__nv_bfloat16*)(sm_ + A_LO_OFF);
    __nv_bfloat16* Bs_hi = (__nv_bfloat16*)(sm_ + B_HI_OFF);
    __nv_bfloat16* Bs_lo = (__nv_bfloat16*)(sm_ + B_LO_OFF);
    float* sb = (float*)(sm_ + SB_OFF);

    int tid = threadIdx.x;
    int warp = tid >> 5, l = tid & 31;
    if (tid < 128) sb[tid] = tvec ? tvec[tid] : g_t0[tid];
    int row0 = blockIdx.x * 128;
    int wm = (warp >> 1) * 32, wn = (warp & 1) * 64;

    const __nv_bfloat16* Whi = g_Whi + layer * 32768;
    const __nv_bfloat16* Wlo = g_Wlo + layer * 32768;

    int ar = tid >> 1, asc = (tid & 1) * 2;
    int bk = tid >> 3, bsc = (tid & 7) * 2;

    auto issue = [&](int s, int buf) {
        const __nv_bfloat16* Ahi = (s < 4) ? g_uhi : g_vhi;
        const __nv_bfloat16* Alo = (s < 4) ? g_ulo : g_vlo;
        int akb = (s & 3) * 32;
        int grow = row0 + ar; if (grow >= NN) grow = NN - 1;
        const __nv_bfloat16* ah = Ahi + grow * 128 + akb + asc * 8;
        const __nv_bfloat16* al = Alo + grow * 128 + akb + asc * 8;
        uint32_t dh = sptr(As_hi + (buf * 128 + ar) * 40 + asc * 8);
        uint32_t dl = sptr(As_lo + (buf * 128 + ar) * 40 + asc * 8);
        CP16(dh, ah); CP16(dh + 16, ah + 8);
        CP16(dl, al); CP16(dl + 16, al + 8);
        const __nv_bfloat16* bh = Whi + (s * 32 + bk) * 128 + bsc * 8;
        const __nv_bfloat16* bl = Wlo + (s * 32 + bk) * 128 + bsc * 8;
        uint32_t eh = sptr(Bs_hi + (buf * 32 + bk) * 136 + bsc * 8);
        uint32_t el = sptr(Bs_lo + (buf * 32 + bk) * 136 + bsc * 8);
        CP16(eh, bh); CP16(eh + 16, bh + 8);
        CP16(el, bl); CP16(el + 16, bl + 8);
        CPCOMMIT();
    };

    float acc[2][8][4];
#pragma unroll
    for (int a = 0; a < 2; a++)
#pragma unroll
        for (int b = 0; b < 8; b++)
#pragma unroll
            for (int c = 0; c < 4; c++) acc[a][b][c] = 0.f;

    int rA = (l & 7) + ((l >> 3) & 1) * 8;
    int cA = (l >> 4) * 8;
    uint32_t aHi0 = sptr(As_hi + (wm + rA) * 40 + cA);
    uint32_t aLo0 = sptr(As_lo + (wm + rA) * 40 + cA);
    uint32_t bHi0 = sptr(Bs_hi + rA * 136 + wn + cA);
    uint32_t bLo0 = sptr(Bs_lo + rA * 136 + wn + cA);

    issue(first_stage, 0);
#pragma unroll 1
    for (int s = first_stage; s < 8; s++) {
        int buf = (s - first_stage) & 1;
        if (s + 1 < 8) issue(s + 1, buf ^ 1);
        if (s + 1 < 8) { CPWAIT(1); } else { CPWAIT(0); }
        __syncthreads();

        uint32_t aHi = aHi0 + buf * ABUF, aLo = aLo0 + buf * ABUF;
        uint32_t bHi = bHi0 + buf * BBUF, bLo = bLo0 + buf * BBUF;
#pragma unroll
        for (int ks = 0; ks < 2; ks++) {
            int k16 = ks * 16;
            uint32_t ah[2][4], al[2][4];
#pragma unroll
            for (int mt = 0; mt < 2; mt++) {
                LDSM4(ah[mt], aHi + (mt * 16 * 40 + k16) * 2);
                LDSM4(al[mt], aLo + (mt * 16 * 40 + k16) * 2);
            }
#pragma unroll
            for (int ng = 0; ng < 4; ng++) {
                uint32_t bh[4], bl[4];
                LDSM4T(bh, bHi + (k16 * 136 + ng * 16) * 2);
                LDSM4T(bl, bLo + (k16 * 136 + ng * 16) * 2);
#pragma unroll
                for (int mt = 0; mt < 2; mt++) {
#pragma unroll
                    for (int sub = 0; sub < 2; sub++) {
                        float* C = acc[mt][ng * 2 + sub];
                        MMA(C, ah[mt], &bh[sub * 2]);
                        MMA(C, ah[mt], &bl[sub * 2]);
                        MMA(C, al[mt], &bh[sub * 2]);
                    }
                }
            }
        }
        __syncthreads();
    }

    int gq = l >> 2, tg = l & 3;
#pragma unroll
    for (int mt = 0; mt < 2; mt++) {
        int r1 = row0 + wm + mt * 16 + gq;
        int r2 = r1 + 8;
        float c1 = (r1 < NN) ? g_c[r1] : 0.f;
        float c2 = (r2 < NN) ? g_c[r2] : 0.f;
#pragma unroll
        for (int nt = 0; nt < 8; nt++) {
            int col = wn + nt * 8 + tg * 2;
            float b0 = sb[col], b1 = sb[col + 1];
            float* C = acc[mt][nt];
            float v0 = fmaxf(C[0] + c1 * b0, 0.f), v1 = fmaxf(C[1] + c1 * b1, 0.f);
            float v2 = fmaxf(C[2] + c2 * b0, 0.f), v3 = fmaxf(C[3] + c2 * b1, 0.f);
            if (r1 < NN) {
                *(float2*)&g_h[r1 * 128 + col] = make_float2(v0, v1);
                *(__half2*)&g_hf[r1 * 128 + col] = __floats2half2_rn(v0, v1);
            }
            if (r2 < NN) {
                *(float2*)&g_h[r2 * 128 + col] = make_float2(v2, v3);
                *(__half2*)&g_hf[r2 * 128 + col] = __floats2half2_rn(v2, v3);
            }
        }
    }
}

// ---------------- fused pool + collapsed last layer + classifier ------------
__device__ __forceinline__ int lower_bound(const int* a, int n, int key) {
    int lo = 0, hi = n;
    while (lo < hi) {
        int mid = (lo + hi) >> 1;
        if (a[mid] < key) lo = mid + 1; else hi = mid;
    }
    return lo;
}

__global__ void k_pool_out(const int* __restrict__ batch,
                           const float* __restrict__ bp,
                           float* __restrict__ out) {
    int g = blockIdx.x, t = threadIdx.x;
    __shared__ int s_lo, s_hi;
    __shared__ float sp[256];
    __shared__ float spc[256];
    if (t == 0) s_lo = lower_bound(batch, NN, g);
    if (t == 1) s_hi = lower_bound(batch, NN, g + 1);
    __syncthreads();
    int lo = s_lo, hi = s_hi;
    float sum = 0.f;
    if (t < 128) {
        for (int r = lo; r < hi; r++) sum += g_u32[r * 128 + t];
    } else {
        int q = t - 128;
        for (int r = lo; r < hi; r++)
            sum += __bfloat162float(g_vhi[r * 128 + q]) + __bfloat162float(g_vlo[r * 128 + q]);
    }
    float csum = 0.f;
    for (int r = lo + t; r < hi; r += 256) csum += g_c[r];
    float inv = 1.f / fmaxf((float)(hi - lo), 1.f);
    sp[t] = sum * inv;
    spc[t] = csum;
    __syncthreads();
#pragma unroll
    for (int s = 128; s > 0; s >>= 1) {
        if (t < s) spc[t] += spc[t + s];
        __syncthreads();
    }
    float pcm = spc[0] * inv;
    if (t < 128) {
        float acc = fmaf(pcm, g_bw[t], bp[t]);
#pragma unroll 8
        for (int k = 0; k < 256; k++) acc = fmaf(sp[k], g_Wcomb[k * 128 + t], acc);
        out[g * 128 + t] = acc;
    }
}

// ---------------- launch ----------------------------------------------------
extern "C" void kernel_launch(void* const* d_in, const int* in_sizes, int n_in,
                              void* d_out, int out_size) {
    const int*   ei    = (const int*)d_in[1];
    const float* ea    = (const float*)d_in[2];
    const int*   batch = (const int*)d_in[3];
    const float* emb   = (const float*)d_in[4];
    const float* Ws    = (const float*)d_in[5];
    const float* bs    = (const float*)d_in[6];
    const float* Wes   = (const float*)d_in[7];
    const float* Wp    = (const float*)d_in[8];
    const float* bp    = (const float*)d_in[9];
    float* out = (float*)d_out;

    static cudaStream_t sB = 0;
    static cudaEvent_t evFork = 0, evPrep = 0;
    static int initialized = 0;
    if (!initialized) {
        initialized = 1;
        cudaFuncSetAttribute(k_gemm, cudaFuncAttributeMaxDynamicSharedMemorySize,
                             GEMM_SMEM);
        bool ok = (cudaStreamCreateWithFlags(&sB, cudaStreamNonBlocking) == cudaSuccess) &&
                  (cudaEventCreateWithFlags(&evFork, cudaEventDisableTiming) == cudaSuccess) &&
                  (cudaEventCreateWithFlags(&evPrep, cudaEventDisableTiming) == cudaSuccess);
        if (!ok) sB = 0;
    }
    bool par = (sB != 0);

    // weight prep on side stream (independent of CSR chain)
    if (par) {
        cudaEventRecord(evFork, 0);
        cudaStreamWaitEvent(sB, evFork, 0);
        k_prep<<<642, 256, 0, sB>>>(Ws, Wes, bs, Wp, emb);
        cudaEventRecord(evPrep, sB);
    } else {
        k_prep<<<642, 256>>>(Ws, Wes, bs, Wp, emb);
    }

    // CSR chain + layers on the main stream, full-grid each
    k_count<<<(NE + 255) / 256, 256>>>(ei);
    k_scan1<<<NBLK, 256>>>();
    k_scan3z<<<NBLK, 256>>>();
    k_fill<<<(NE + 255) / 256, 256>>>(ei);
    k_v<<<GR_SPMM, 256>>>(ea);

    if (par) cudaStreamWaitEvent(0, evPrep, 0);   // weights/t0 ready
    // layer 0: rank-1 shortcut, K=128 (v@We0 only)
    k_gemm<<<NTILE, 256, GEMM_SMEM>>>(0, 4, nullptr);
    // layers 1..3
    for (int l = 1; l < 4; l++) {
        k_spmm_split<<<GR_SPMM, 256>>>();
        k_gemm<<<NTILE, 256, GEMM_SMEM>>>(l, 0, bs + l * 128);
    }
    // layer 4 collapsed into pooled path
    k_spmm_f32<<<GR_SPMM, 256>>>();
    k_pool_out<<<NG, 256>>>(batch, bp, out);
}

// round 15
// speedup vs baseline: 1.1145x; 1.1145x over previous
#include <cuda_runtime.h>
#include <cuda_bf16.h>
#include <cstdint>

#define NN 50000
#define NE 640000
#define D  128
#define NG 512
#define NBLK ((NN + 255) / 256)
#define NTILE ((NN + 127) / 128)
#define GR_SPMM ((NN * 32 + 255) / 256)

// dynamic smem layout for k_gemm (bytes)
#define A_HI_OFF 0        // [2][128][40] bf16 : 2*10240
#define A_LO_OFF 20480
#define B_HI_OFF 40960    // [2][32][136] bf16 : 2*8704
#define B_LO_OFF 58368
#define SB_OFF   75776    // float[128]
#define GEMM_SMEM 76288
#define ABUF 10240
#define BBUF 8704

// ---------------- scratch (static device globals) --------------------------
__device__ __align__(16) float g_h[NN * D];
__device__ __align__(16) float g_u32[NN * D];
__device__ __align__(16) __nv_bfloat16 g_uhi[NN * D];
__device__ __align__(16) __nv_bfloat16 g_ulo[NN * D];
__device__ __align__(16) __nv_bfloat16 g_vhi[NN * D];
__device__ __align__(16) __nv_bfloat16 g_vlo[NN * D];
__device__ __align__(16) __nv_bfloat16 g_Whi[4 * 256 * 128];
__device__ __align__(16) __nv_bfloat16 g_Wlo[4 * 256 * 128];
__device__ __align__(16) float g_Wcomb[256 * 128];
__device__ float g_bw[128];
__device__ float g_t0[128];
__device__ float g_invdeg[NN];
__device__ float g_c[NN];
__device__ int   g_indeg[NN];
__device__ int   g_rowptr[NN + 1];
__device__ int   g_fill[NN];
__device__ int   g_bsum[NBLK + 32];
__device__ __align__(8) int2 g_csr[NE];     // (src, eid)

// ---------------- helpers ---------------------------------------------------
__device__ __forceinline__ unsigned short bf_bits(__nv_bfloat16 h) {
    unsigned short u; memcpy(&u, &h, 2); return u;
}
__device__ __forceinline__ void split4(float4 a, uint2& hi, uint2& lo) {
    __nv_bfloat16 h0 = __float2bfloat16(a.x), h1 = __float2bfloat16(a.y);
    __nv_bfloat16 h2 = __float2bfloat16(a.z), h3 = __float2bfloat16(a.w);
    __nv_bfloat16 l0 = __float2bfloat16(a.x - __bfloat162float(h0));
    __nv_bfloat16 l1 = __float2bfloat16(a.y - __bfloat162float(h1));
    __nv_bfloat16 l2 = __float2bfloat16(a.z - __bfloat162float(h2));
    __nv_bfloat16 l3 = __float2bfloat16(a.w - __bfloat162float(h3));
    hi.x = (unsigned)bf_bits(h0) | ((unsigned)bf_bits(h1) << 16);
    hi.y = (unsigned)bf_bits(h2) | ((unsigned)bf_bits(h3) << 16);
    lo.x = (unsigned)bf_bits(l0) | ((unsigned)bf_bits(l1) << 16);
    lo.y = (unsigned)bf_bits(l2) | ((unsigned)bf_bits(l3) << 16);
}
__device__ __forceinline__ uint32_t sptr(const void* p) {
    return (uint32_t)__cvta_generic_to_shared(p);
}

#define LDSM4(R, addr) \
    asm volatile("ldmatrix.sync.aligned.m8n8.x4.shared.b16 {%0,%1,%2,%3},[%4];" \
        : "=r"((R)[0]), "=r"((R)[1]), "=r"((R)[2]), "=r"((R)[3]) : "r"(addr))
#define LDSM4T(R, addr) \
    asm volatile("ldmatrix.sync.aligned.m8n8.x4.trans.shared.b16 {%0,%1,%2,%3},[%4];" \
        : "=r"((R)[0]), "=r"((R)[1]), "=r"((R)[2]), "=r"((R)[3]) : "r"(addr))
#define MMA(C, A, B) \
    asm volatile("mma.sync.aligned.m16n8k16.row.col.f32.bf16.bf16.f32 " \
        "{%0,%1,%2,%3},{%4,%5,%6,%7},{%8,%9},{%0,%1,%2,%3};" \
        : "+f"((C)[0]), "+f"((C)[1]), "+f"((C)[2]), "+f"((C)[3]) \
        : "r"((A)[0]), "r"((A)[1]), "r"((A)[2]), "r"((A)[3]), "r"((B)[0]), "r"((B)[1]))
#define CP16(dst, src) \
    asm volatile("cp.async.cg.shared.global [%0], [%1], 16;" :: "r"(dst), "l"(src))
#define CPCOMMIT() asm volatile("cp.async.commit_group;")
#define CPWAIT(n)  asm volatile("cp.async.wait_group %0;" :: "n"(n))

// ---------------- init / CSR build -----------------------------------------
__global__ void k_zero() {
    int i = blockIdx.x * blockDim.x + threadIdx.x;
    if (i < NN) g_indeg[i] = 0;
}
__global__ void k_count(const int* __restrict__ ei) {
    int e = blockIdx.x * blockDim.x + threadIdx.x;
    if (e < NE) atomicAdd(&g_indeg[ei[NE + e]], 1);
}
__global__ void k_scan1() {
    __shared__ int sm[8];
    int t = threadIdx.x, lane = t & 31, wid = t >> 5;
    int i = blockIdx.x * 256 + t;
    int v = (i < NN) ? g_indeg[i] : 0;
#pragma unroll
    for (int s = 16; s > 0; s >>= 1) v += __shfl_down_sync(0xffffffffu, v, s);
    if (lane == 0) sm[wid] = v;
    __syncthreads();
    if (t == 0) {
        int s = 0;
#pragma unroll
        for (int w = 0; w < 8; w++) s += sm[w];
        g_bsum[blockIdx.x] = s;
    }
}
// block-local scan + in-kernel offset reduction; also invdeg/c and fill=0
__global__ void k_scan3z() {
    __shared__ int red[8];
    __shared__ int ws[8];
    __shared__ int s_base, s_tot;
    int t = threadIdx.x, lane = t & 31, wid = t >> 5;
    int part = 0;
    for (int j = t; j < blockIdx.x; j += 256) part += g_bsum[j];
#pragma unroll
    for (int s = 16; s > 0; s >>= 1) part += __shfl_down_sync(0xffffffffu, part, s);
    if (lane == 0) red[wid] = part;
    __syncthreads();
    if (t == 0) {
        int b = 0;
#pragma unroll
        for (int w = 0; w < 8; w++) b += red[w];
        s_base = b;
    }
    int i = blockIdx.x * 256 + t;
    int v = (i < NN) ? g_indeg[i] : 0;
    int x = v;
#pragma unroll
    for (int s = 1; s < 32; s <<= 1) {
        int tt = __shfl_up_sync(0xffffffffu, x, s);
        if (lane >= s) x += tt;
    }
    if (lane == 31) ws[wid] = x;
    __syncthreads();
    if (t == 0) {
        int acc = 0;
#pragma unroll
        for (int w = 0; w < 8; w++) { int tmp = ws[w]; ws[w] = acc; acc += tmp; }
        s_tot = acc;
    }
    __syncthreads();
    if (i < NN) {
        g_rowptr[i] = s_base + ws[wid] + x - v;
        g_invdeg[i] = 1.0f / fmaxf((float)v, 1.0f);
        g_c[i] = (v > 0) ? 2.0f : 1.0f;
        g_fill[i] = 0;
    }
    if (blockIdx.x == NBLK - 1 && t == 0) g_rowptr[NN] = s_base + s_tot;
}
__global__ void k_fill(const int* __restrict__ ei) {
    int e = blockIdx.x * blockDim.x + threadIdx.x;
    if (e < NE) {
        int dst = ei[NE + e];
        int p = g_rowptr[dst] + atomicAdd(&g_fill[dst], 1);
        g_csr[p] = make_int2(ei[e], e);
    }
}

// merged weight prep: wsplit (blocks 0..511), r0 (512), bw (513), comb (514..641)
__global__ void k_prep(const float* __restrict__ Ws, const float* __restrict__ Wes,
                       const float* __restrict__ bs, const float* __restrict__ Wp,
                       const float* __restrict__ emb) {
    int b = blockIdx.x;
    if (b < 512) {
        int i = b * 256 + threadIdx.x;
        int l = i >> 15, rem = i & 32767;
        int k = rem >> 7, n = rem & 127;
        float v = (k < 128) ? Ws[l * 16384 + k * 128 + n]
                            : Wes[l * 16384 + (k - 128) * 128 + n];
        __nv_bfloat16 h = __float2bfloat16(v);
        g_Whi[i] = h;
        g_Wlo[i] = __float2bfloat16(v - __bfloat162float(h));
    } else if (b == 512) {
        int t = threadIdx.x;
        if (t < 128) {
            float acc = bs[t];
#pragma unroll 8
            for (int k = 0; k < 128; k++) acc = fmaf(emb[k], Ws[k * 128 + t], acc);
            g_t0[t] = acc;
        }
    } else if (b == 513) {
        int t = threadIdx.x;
        if (t < 128) {
            float acc = 0.f;
#pragma unroll 8
            for (int k = 0; k < 128; k++) acc = fmaf(bs[4 * 128 + k], Wp[k * 128 + t], acc);
            g_bw[t] = acc;
        }
    } else {
        int i = (b - 514) * 256 + threadIdx.x;
        int r = i >> 7, c = i & 127;
        const float* Wrow = (r < 128) ? (Ws + 4 * 16384 + r * 128)
                                      : (Wes + 4 * 16384 + (r - 128) * 128);
        float acc = 0.f;
#pragma unroll 8
        for (int k = 0; k < 128; k++) acc = fmaf(Wrow[k], Wp[k * 128 + c], acc);
        g_Wcomb[i] = acc;
    }
}

// V[i] = (sum edge_attr)/deg -> split bf16
__global__ void k_v(const float* __restrict__ ea) {
    int gt = blockIdx.x * blockDim.x + threadIdx.x;
    int w = gt >> 5, lane = gt & 31;
    if (w >= NN) return;
    int s = g_rowptr[w], t = g_rowptr[w + 1];
    float4 acc = make_float4(0.f, 0.f, 0.f, 0.f);
    const float4* ea4 = (const float4*)ea;
    int p = s;
    for (; p + 1 < t; p += 2) {
        int2 c0 = g_csr[p], c1 = g_csr[p + 1];
        float4 x0 = ea4[c0.y * 32 + lane];
        float4 x1 = ea4[c1.y * 32 + lane];
        acc.x += x0.x + x1.x; acc.y += x0.y + x1.y;
        acc.z += x0.z + x1.z; acc.w += x0.w + x1.w;
    }
    if (p < t) {
        float4 x0 = ea4[g_csr[p].y * 32 + lane];
        acc.x += x0.x; acc.y += x0.y; acc.z += x0.z; acc.w += x0.w;
    }
    float id = g_invdeg[w];
    acc.x *= id; acc.y *= id; acc.z *= id; acc.w *= id;
    uint2 hi, lo; split4(acc, hi, lo);
    ((uint2*)g_vhi)[w * 32 + lane] = hi;
    ((uint2*)g_vlo)[w * 32 + lane] = lo;
}

// u = h + (sum h[src])/deg -> split bf16
__global__ void k_spmm_split() {
    int gt = blockIdx.x * blockDim.x + threadIdx.x;
    int w = gt >> 5, lane = gt & 31;
    if (w >= NN) return;
    int s = g_rowptr[w], t = g_rowptr[w + 1];
    float4 acc = make_float4(0.f, 0.f, 0.f, 0.f);
    const float4* h4 = (const float4*)g_h;
    int p = s;
    for (; p + 1 < t; p += 2) {
        int2 c0 = g_csr[p], c1 = g_csr[p + 1];
        float4 x0 = h4[c0.x * 32 + lane];
        float4 x1 = h4[c1.x * 32 + lane];
        acc.x += x0.x + x1.x; acc.y += x0.y + x1.y;
        acc.z += x0.z + x1.z; acc.w += x0.w + x1.w;
    }
    if (p < t) {
        float4 x0 = h4[g_csr[p].x * 32 + lane];
        acc.x += x0.x; acc.y += x0.y; acc.z += x0.z; acc.w += x0.w;
    }
    float id = g_invdeg[w];
    float4 hh = h4[w * 32 + lane];
    acc.x = hh.x + acc.x * id; acc.y = hh.y + acc.y * id;
    acc.z = hh.z + acc.z * id; acc.w = hh.w + acc.w * id;
    uint2 hi, lo; split4(acc, hi, lo);
    ((uint2*)g_uhi)[w * 32 + lane] = hi;
    ((uint2*)g_ulo)[w * 32 + lane] = lo;
}

// u (layer 4) -> fp32 for pooled path
__global__ void k_spmm_f32() {
    int gt = blockIdx.x * blockDim.x + threadIdx.x;
    int w = gt >> 5, lane = gt & 31;
    if (w >= NN) return;
    int s = g_rowptr[w], t = g_rowptr[w + 1];
    float4 acc = make_float4(0.f, 0.f, 0.f, 0.f);
    const float4* h4 = (const float4*)g_h;
    int p = s;
    for (; p + 1 < t; p += 2) {
        int2 c0 = g_csr[p], c1 = g_csr[p + 1];
        float4 x0 = h4[c0.x * 32 + lane];
        float4 x1 = h4[c1.x * 32 + lane];
        acc.x += x0.x + x1.x; acc.y += x0.y + x1.y;
        acc.z += x0.z + x1.z; acc.w += x0.w + x1.w;
    }
    if (p < t) {
        float4 x0 = h4[g_csr[p].x * 32 + lane];
        acc.x += x0.x; acc.y += x0.y; acc.z += x0.z; acc.w += x0.w;
    }
    float id = g_invdeg[w];
    float4 hh = h4[w * 32 + lane];
    acc.x = hh.x + acc.x * id; acc.y = hh.y + acc.y * id;
    acc.z = hh.z + acc.z * id; acc.w = hh.w + acc.w * id;
    ((float4*)g_u32)[w * 32 + lane] = acc;
}

// g_h = relu( [u|v] @ [W;We] + c*t )  — bf16x3 mma, cp.async double-buffered.
__global__ __launch_bounds__(256, 2) void k_gemm(int layer, int first_stage,
                                                 const float* __restrict__ tvec) {
    extern __shared__ char sm_[];
    __nv_bfloat16* As_hi = (__nv_bfloat16*)(sm_ + A_HI_OFF);
    __nv_bfloat16* As_lo = (__nv_bfloat16*)(sm_ + A_LO_OFF);
    __nv_bfloat16* Bs_hi = (__nv_bfloat16*)(sm_ + B_HI_OFF);
    __nv_bfloat16* Bs_lo = (__nv_bfloat16*)(sm_ + B_LO_OFF);
    float* sb = (float*)(sm_ + SB_OFF);

    int tid = threadIdx.x;
    int warp = tid >> 5, l = tid & 31;
    if (tid < 128) sb[tid] = tvec ? tvec[tid] : g_t0[tid];
    int row0 = blockIdx.x * 128;
    int wm = (warp >> 1) * 32, wn = (warp & 1) * 64;

    const __nv_bfloat16* Whi = g_Whi + layer * 32768;
    const __nv_bfloat16* Wlo = g_Wlo + layer * 32768;

    int ar = tid >> 1, asc = (tid & 1) * 2;
    int bk = tid >> 3, bsc = (tid & 7) * 2;

    auto issue = [&](int s, int buf) {
        const __nv_bfloat16* Ahi = (s < 4) ? g_uhi : g_vhi;
        const __nv_bfloat16* Alo = (s < 4) ? g_ulo : g_vlo;
        int akb = (s & 3) * 32;
        int grow = row0 + ar; if (grow >= NN) grow = NN - 1;
        const __nv_bfloat16* ah = Ahi + grow * 128 + akb + asc * 8;
        const __nv_bfloat16* al = Alo + grow * 128 + akb + asc * 8;
        uint32_t dh = sptr(As_hi + (buf * 128 + ar) * 40 + asc * 8);
        uint32_t dl = sptr(As_lo + (buf * 128 + ar) * 40 + asc * 8);
        CP16(dh, ah); CP16(dh + 16, ah + 8);
        CP16(dl, al); CP16(dl + 16, al + 8);
        const __nv_bfloat16* bh = Whi + (s * 32 + bk) * 128 + bsc * 8;
        const __nv_bfloat16* bl = Wlo + (s * 32 + bk) * 128 + bsc * 8;
        uint32_t eh = sptr(Bs_hi + (buf * 32 + bk) * 136 + bsc * 8);
        uint32_t el = sptr(Bs_lo + (buf * 32 + bk) * 136 + bsc * 8);
        CP16(eh, bh); CP16(eh + 16, bh + 8);
        CP16(el, bl); CP16(el + 16, bl + 8);
        CPCOMMIT();
    };

    float acc[2][8][4];
#pragma unroll
    for (int a = 0; a < 2; a++)
#pragma unroll
        for (int b = 0; b < 8; b++)
#pragma unroll
            for (int c = 0; c < 4; c++) acc[a][b][c] = 0.f;

    int rA = (l & 7) + ((l >> 3) & 1) * 8;
    int cA = (l >> 4) * 8;
    uint32_t aHi0 = sptr(As_hi + (wm + rA) * 40 + cA);
    uint32_t aLo0 = sptr(As_lo + (wm + rA) * 40 + cA);
    uint32_t bHi0 = sptr(Bs_hi + rA * 136 + wn + cA);
    uint32_t bLo0 = sptr(Bs_lo + rA * 136 + wn + cA);

    issue(first_stage, 0);
#pragma unroll 1
    for (int s = first_stage; s < 8; s++) {
        int buf = (s - first_stage) & 1;
        if (s + 1 < 8) issue(s + 1, buf ^ 1);
        if (s + 1 < 8) { CPWAIT(1); } else { CPWAIT(0); }
        __syncthreads();

        uint32_t aHi = aHi0 + buf * ABUF, aLo = aLo0 + buf * ABUF;
        uint32_t bHi = bHi0 + buf * BBUF, bLo = bLo0 + buf * BBUF;
#pragma unroll
        for (int ks = 0; ks < 2; ks++) {
            int k16 = ks * 16;
            uint32_t ah[2][4], al[2][4];
#pragma unroll
            for (int mt = 0; mt < 2; mt++) {
                LDSM4(ah[mt], aHi + (mt * 16 * 40 + k16) * 2);
                LDSM4(al[mt], aLo + (mt * 16 * 40 + k16) * 2);
            }
#pragma unroll
            for (int ng = 0; ng < 4; ng++) {
                uint32_t bh[4], bl[4];
                LDSM4T(bh, bHi + (k16 * 136 + ng * 16) * 2);
                LDSM4T(bl, bLo + (k16 * 136 + ng * 16) * 2);
#pragma unroll
                for (int mt = 0; mt < 2; mt++) {
#pragma unroll
                    for (int sub = 0; sub < 2; sub++) {
                        float* C = acc[mt][ng * 2 + sub];
                        MMA(C, ah[mt], &bh[sub * 2]);
                        MMA(C, ah[mt], &bl[sub * 2]);
                        MMA(C, al[mt], &bh[sub * 2]);
                    }
                }
            }
        }
        __syncthreads();
    }

    int gq = l >> 2, tg = l & 3;
#pragma unroll
    for (int mt = 0; mt < 2; mt++) {
        int r1 = row0 + wm + mt * 16 + gq;
        int r2 = r1 + 8;
        float c1 = (r1 < NN) ? g_c[r1] : 0.f;
        float c2 = (r2 < NN) ? g_c[r2] : 0.f;
#pragma unroll
        for (int nt = 0; nt < 8; nt++) {
            int col = wn + nt * 8 + tg * 2;
            float b0 = sb[col], b1 = sb[col + 1];
            float* C = acc[mt][nt];
            float v0 = fmaxf(C[0] + c1 * b0, 0.f), v1 = fmaxf(C[1] + c1 * b1, 0.f);
            float v2 = fmaxf(C[2] + c2 * b0, 0.f), v3 = fmaxf(C[3] + c2 * b1, 0.f);
            if (r1 < NN) *(float2*)&g_h[r1 * 128 + col] = make_float2(v0, v1);
            if (r2 < NN) *(float2*)&g_h[r2 * 128 + col] = make_float2(v2, v3);
        }
    }
}

// ---------------- fused pool + collapsed last layer + classifier ------------
__device__ __forceinline__ int lower_bound(const int* a, int n, int key) {
    int lo = 0, hi = n;
    while (lo < hi) {
        int mid = (lo + hi) >> 1;
        if (a[mid] < key) lo = mid + 1; else hi = mid;
    }
    return lo;
}

__global__ void k_pool_out(const int* __restrict__ batch,
                           const float* __restrict__ bp,
                           float* __restrict__ out) {
    int g = blockIdx.x, t = threadIdx.x;
    __shared__ int s_lo, s_hi;
    __shared__ float sp[256];
    __shared__ float spc[256];
    if (t == 0) s_lo = lower_bound(batch, NN, g);
    if (t == 1) s_hi = lower_bound(batch, NN, g + 1);
    __syncthreads();
    int lo = s_lo, hi = s_hi;
    float sum = 0.f;
    if (t < 128) {
        for (int r = lo; r < hi; r++) sum += g_u32[r * 128 + t];
    } else {
        int q = t - 128;
        for (int r = lo; r < hi; r++)
            sum += __bfloat162float(g_vhi[r * 128 + q]) + __bfloat162float(g_vlo[r * 128 + q]);
    }
    float csum = 0.f;
    for (int r = lo + t; r < hi; r += 256) csum += g_c[r];
    float inv = 1.f / fmaxf((float)(hi - lo), 1.f);
    sp[t] = sum * inv;
    spc[t] = csum;
    __syncthreads();
#pragma unroll
    for (int s = 128; s > 0; s >>= 1) {
        if (t < s) spc[t] += spc[t + s];
        __syncthreads();
    }
    float pcm = spc[0] * inv;
    if (t < 128) {
        float acc = fmaf(pcm, g_bw[t], bp[t]);
#pragma unroll 8
        for (int k = 0; k < 256; k++) acc = fmaf(sp[k], g_Wcomb[k * 128 + t], acc);
        out[g * 128 + t] = acc;
    }
}

// ---------------- launch ----------------------------------------------------
extern "C" void kernel_launch(void* const* d_in, const int* in_sizes, int n_in,
                              void* d_out, int out_size) {
    const int*   ei    = (const int*)d_in[1];
    const float* ea    = (const float*)d_in[2];
    const int*   batch = (const int*)d_in[3];
    const float* emb   = (const float*)d_in[4];
    const float* Ws    = (const float*)d_in[5];
    const float* bs    = (const float*)d_in[6];
    const float* Wes   = (const float*)d_in[7];
    const float* Wp    = (const float*)d_in[8];
    const float* bp    = (const float*)d_in[9];
    float* out = (float*)d_out;

    static cudaStream_t sB = 0;
    static cudaEvent_t evFork = 0, evPrep = 0;
    static int initialized = 0;
    if (!initialized) {
        initialized = 1;
        cudaFuncSetAttribute(k_gemm, cudaFuncAttributeMaxDynamicSharedMemorySize,
                             GEMM_SMEM);
        bool ok = (cudaStreamCreateWithFlags(&sB, cudaStreamNonBlocking) == cudaSuccess) &&
                  (cudaEventCreateWithFlags(&evFork, cudaEventDisableTiming) == cudaSuccess) &&
                  (cudaEventCreateWithFlags(&evPrep, cudaEventDisableTiming) == cudaSuccess);
        if (!ok) sB = 0;
    }
    bool par = (sB != 0);

    // weight prep on side stream (independent of CSR chain)
    if (par) {
        cudaEventRecord(evFork, 0);
        cudaStreamWaitEvent(sB, evFork, 0);
        k_prep<<<642, 256, 0, sB>>>(Ws, Wes, bs, Wp, emb);
        cudaEventRecord(evPrep, sB);
    } else {
        k_prep<<<642, 256>>>(Ws, Wes, bs, Wp, emb);
    }

    // CSR chain + layers on the main stream, full-grid each
    k_zero<<<NBLK, 256>>>();
    k_count<<<(NE + 255) / 256, 256>>>(ei);
    k_scan1<<<NBLK, 256>>>();
    k_scan3z<<<NBLK, 256>>>();
    k_fill<<<(NE + 255) / 256, 256>>>(ei);
    k_v<<<GR_SPMM, 256>>>(ea);

    if (par) cudaStreamWaitEvent(0, evPrep, 0);   // weights/t0 ready
    // layer 0: rank-1 shortcut, K=128 (v@We0 only)
    k_gemm<<<NTILE, 256, GEMM_SMEM>>>(0, 4, nullptr);
    // layers 1..3
    for (int l = 1; l < 4; l++) {
        k_spmm_split<<<GR_SPMM, 256>>>();
        k_gemm<<<NTILE, 256, GEMM_SMEM>>>(l, 0, bs + l * 128);
    }
    // layer 4 collapsed into pooled path
    k_spmm_f32<<<GR_SPMM, 256>>>();
    k_pool_out<<<NG, 256>>>(batch, bp, out);
}

// round 17
// speedup vs baseline: 1.2458x; 1.1178x over previous
#include <cuda_runtime.h>
#include <cuda_bf16.h>
#include <cuda_fp16.h>
#include <cstdint>

#define NN 50000
#define NE 640000
#define D  128
#define NG 512
#define NBLK ((NN + 255) / 256)
#define NTILE ((NN + 127) / 128)
#define GR_SPMM ((NN * 32 + 255) / 256)

// dynamic smem layout for k_gemm (bytes)
#define A_OFF    0        // [2][128][40] fp16 : 2*10240
#define B_HI_OFF 20480    // [2][32][136] fp16 : 2*8704
#define B_LO_OFF 37888
#define SB_OFF   55296    // float[128]
#define GEMM_SMEM 55808
#define ABUF 10240
#define BBUF 8704

// ---------------- scratch (static device globals) --------------------------
__device__ __align__(16) float g_h[NN * D];
__device__ __align__(16) float g_u32[NN * D];
__device__ __align__(16) __half g_uf[NN * D];      // A operand (u), fp16
__device__ __align__(16) __half g_vf[NN * D];      // A operand (v), fp16
__device__ __align__(16) __half g_Whi[4 * 256 * 128];
__device__ __align__(16) __half g_Wlo[4 * 256 * 128];
__device__ __align__(16) float g_Wcomb[256 * 128];
__device__ float g_bw[128];
__device__ float g_t0[128];
__device__ float g_invdeg[NN];
__device__ float g_c[NN];
__device__ int   g_indeg[NN];
__device__ int   g_rowptr[NN + 1];
__device__ int   g_fill[NN];
__device__ int   g_bsum[NBLK + 32];
__device__ __align__(8) int2 g_csr[NE];     // (src, eid)

// ---------------- helpers ---------------------------------------------------
__device__ __forceinline__ uint2 pack4h(float4 a) {
    uint2 r;
    *(__half2*)&r.x = __floats2half2_rn(a.x, a.y);
    *(__half2*)&r.y = __floats2half2_rn(a.z, a.w);
    return r;
}
__device__ __forceinline__ uint32_t sptr(const void* p) {
    return (uint32_t)__cvta_generic_to_shared(p);
}

#define LDSM4(R, addr) \
    asm volatile("ldmatrix.sync.aligned.m8n8.x4.shared.b16 {%0,%1,%2,%3},[%4];" \
        : "=r"((R)[0]), "=r"((R)[1]), "=r"((R)[2]), "=r"((R)[3]) : "r"(addr))
#define LDSM4T(R, addr) \
    asm volatile("ldmatrix.sync.aligned.m8n8.x4.trans.shared.b16 {%0,%1,%2,%3},[%4];" \
        : "=r"((R)[0]), "=r"((R)[1]), "=r"((R)[2]), "=r"((R)[3]) : "r"(addr))
#define MMA(C, A, B) \
    asm volatile("mma.sync.aligned.m16n8k16.row.col.f32.f16.f16.f32 " \
        "{%0,%1,%2,%3},{%4,%5,%6,%7},{%8,%9},{%0,%1,%2,%3};" \
        : "+f"((C)[0]), "+f"((C)[1]), "+f"((C)[2]), "+f"((C)[3]) \
        : "r"((A)[0]), "r"((A)[1]), "r"((A)[2]), "r"((A)[3]), "r"((B)[0]), "r"((B)[1]))
#define CP16(dst, src) \
    asm volatile("cp.async.cg.shared.global [%0], [%1], 16;" :: "r"(dst), "l"(src))
#define CPCOMMIT() asm volatile("cp.async.commit_group;")
#define CPWAIT(n)  asm volatile("cp.async.wait_group %0;" :: "n"(n))

// ---------------- init / CSR build -----------------------------------------
__global__ void k_zero() {
    int i = blockIdx.x * blockDim.x + threadIdx.x;
    if (i < NN) g_indeg[i] = 0;
}
__global__ void k_count(const int* __restrict__ ei) {
    int e = blockIdx.x * blockDim.x + threadIdx.x;
    if (e < NE) atomicAdd(&g_indeg[ei[NE + e]], 1);
}
__global__ void k_scan1() {
    __shared__ int sm[8];
    int t = threadIdx.x, lane = t & 31, wid = t >> 5;
    int i = blockIdx.x * 256 + t;
    int v = (i < NN) ? g_indeg[i] : 0;
#pragma unroll
    for (int s = 16; s > 0; s >>= 1) v += __shfl_down_sync(0xffffffffu, v, s);
    if (lane == 0) sm[wid] = v;
    __syncthreads();
    if (t == 0) {
        int s = 0;
#pragma unroll
        for (int w = 0; w < 8; w++) s += sm[w];
        g_bsum[blockIdx.x] = s;
    }
}
__global__ void k_scan3z() {
    __shared__ int red[8];
    __shared__ int ws[8];
    __shared__ int s_base, s_tot;
    int t = threadIdx.x, lane = t & 31, wid = t >> 5;
    int part = 0;
    for (int j = t; j < blockIdx.x; j += 256) part += g_bsum[j];
#pragma unroll
    for (int s = 16; s > 0; s >>= 1) part += __shfl_down_sync(0xffffffffu, part, s);
    if (lane == 0) red[wid] = part;
    __syncthreads();
    if (t == 0) {
        int b = 0;
#pragma unroll
        for (int w = 0; w < 8; w++) b += red[w];
        s_base = b;
    }
    int i = blockIdx.x * 256 + t;
    int v = (i < NN) ? g_indeg[i] : 0;
    int x = v;
#pragma unroll
    for (int s = 1; s < 32; s <<= 1) {
        int tt = __shfl_up_sync(0xffffffffu, x, s);
        if (lane >= s) x += tt;
    }
    if (lane == 31) ws[wid] = x;
    __syncthreads();
    if (t == 0) {
        int acc = 0;
#pragma unroll
        for (int w = 0; w < 8; w++) { int tmp = ws[w]; ws[w] = acc; acc += tmp; }
        s_tot = acc;
    }
    __syncthreads();
    if (i < NN) {
        g_rowptr[i] = s_base + ws[wid] + x - v;
        g_invdeg[i] = 1.0f / fmaxf((float)v, 1.0f);
        g_c[i] = (v > 0) ? 2.0f : 1.0f;
        g_fill[i] = 0;
    }
    if (blockIdx.x == NBLK - 1 && t == 0) g_rowptr[NN] = s_base + s_tot;
}
__global__ void k_fill(const int* __restrict__ ei) {
    int e = blockIdx.x * blockDim.x + threadIdx.x;
    if (e < NE) {
        int dst = ei[NE + e];
        int p = g_rowptr[dst] + atomicAdd(&g_fill[dst], 1);
        g_csr[p] = make_int2(ei[e], e);
    }
}

// merged weight prep: wsplit fp16 hi/lo (blocks 0..511), r0 (512), bw (513),
// comb (514..641)
__global__ void k_prep(const float* __restrict__ Ws, const float* __restrict__ Wes,
                       const float* __restrict__ bs, const float* __restrict__ Wp,
                       const float* __restrict__ emb) {
    int b = blockIdx.x;
    if (b < 512) {
        int i = b * 256 + threadIdx.x;
        int l = i >> 15, rem = i & 32767;
        int k = rem >> 7, n = rem & 127;
        float v = (k < 128) ? Ws[l * 16384 + k * 128 + n]
                            : Wes[l * 16384 + (k - 128) * 128 + n];
        __half h = __float2half_rn(v);
        g_Whi[i] = h;
        g_Wlo[i] = __float2half_rn(v - __half2float(h));
    } else if (b == 512) {
        int t = threadIdx.x;
        if (t < 128) {
            float acc = bs[t];
#pragma unroll 8
            for (int k = 0; k < 128; k++) acc = fmaf(emb[k], Ws[k * 128 + t], acc);
            g_t0[t] = acc;
        }
    } else if (b == 513) {
        int t = threadIdx.x;
        if (t < 128) {
            float acc = 0.f;
#pragma unroll 8
            for (int k = 0; k < 128; k++) acc = fmaf(bs[4 * 128 + k], Wp[k * 128 + t], acc);
            g_bw[t] = acc;
        }
    } else {
        int i = (b - 514) * 256 + threadIdx.x;
        int r = i >> 7, c = i & 127;
        const float* Wrow = (r < 128) ? (Ws + 4 * 16384 + r * 128)
                                      : (Wes + 4 * 16384 + (r - 128) * 128);
        float acc = 0.f;
#pragma unroll 8
        for (int k = 0; k < 128; k++) acc = fmaf(Wrow[k], Wp[k * 128 + c], acc);
        g_Wcomb[i] = acc;
    }
}

// V[i] = (sum edge_attr)/deg -> fp16
__global__ void k_v(const float* __restrict__ ea) {
    int gt = blockIdx.x * blockDim.x + threadIdx.x;
    int w = gt >> 5, lane = gt & 31;
    if (w >= NN) return;
    int s = g_rowptr[w], t = g_rowptr[w + 1];
    float4 acc = make_float4(0.f, 0.f, 0.f, 0.f);
    const float4* ea4 = (const float4*)ea;
    int p = s;
    for (; p + 1 < t; p += 2) {
        int2 c0 = g_csr[p], c1 = g_csr[p + 1];
        float4 x0 = ea4[c0.y * 32 + lane];
        float4 x1 = ea4[c1.y * 32 + lane];
        acc.x += x0.x + x1.x; acc.y += x0.y + x1.y;
        acc.z += x0.z + x1.z; acc.w += x0.w + x1.w;
    }
    if (p < t) {
        float4 x0 = ea4[g_csr[p].y * 32 + lane];
        acc.x += x0.x; acc.y += x0.y; acc.z += x0.z; acc.w += x0.w;
    }
    float id = g_invdeg[w];
    acc.x *= id; acc.y *= id; acc.z *= id; acc.w *= id;
    ((uint2*)g_vf)[w * 32 + lane] = pack4h(acc);
}

// u = h + (sum h[src])/deg -> fp16
__global__ void k_spmm_split() {
    int gt = blockIdx.x * blockDim.x + threadIdx.x;
    int w = gt >> 5, lane = gt & 31;
    if (w >= NN) return;
    int s = g_rowptr[w], t = g_rowptr[w + 1];
    float4 acc = make_float4(0.f, 0.f, 0.f, 0.f);
    const float4* h4 = (const float4*)g_h;
    int p = s;
    for (; p + 1 < t; p += 2) {
        int2 c0 = g_csr[p], c1 = g_csr[p + 1];
        float4 x0 = h4[c0.x * 32 + lane];
        float4 x1 = h4[c1.x * 32 + lane];
        acc.x += x0.x + x1.x; acc.y += x0.y + x1.y;
        acc.z += x0.z + x1.z; acc.w += x0.w + x1.w;
    }
    if (p < t) {
        float4 x0 = h4[g_csr[p].x * 32 + lane];
        acc.x += x0.x; acc.y += x0.y; acc.z += x0.z; acc.w += x0.w;
    }
    float id = g_invdeg[w];
    float4 hh = h4[w * 32 + lane];
    acc.x = hh.x + acc.x * id; acc.y = hh.y + acc.y * id;
    acc.z = hh.z + acc.z * id; acc.w = hh.w + acc.w * id;
    ((uint2*)g_uf)[w * 32 + lane] = pack4h(acc);
}

// u (layer 4) -> fp32 for pooled path
__global__ void k_spmm_f32() {
    int gt = blockIdx.x * blockDim.x + threadIdx.x;
    int w = gt >> 5, lane = gt & 31;
    if (w >= NN) return;
    int s = g_rowptr[w], t = g_rowptr[w + 1];
    float4 acc = make_float4(0.f, 0.f, 0.f, 0.f);
    const float4* h4 = (const float4*)g_h;
    int p = s;
    for (; p + 1 < t; p += 2) {
        int2 c0 = g_csr[p], c1 = g_csr[p + 1];
        float4 x0 = h4[c0.x * 32 + lane];
        float4 x1 = h4[c1.x * 32 + lane];
        acc.x += x0.x + x1.x; acc.y += x0.y + x1.y;
        acc.z += x0.z + x1.z; acc.w += x0.w + x1.w;
    }
    if (p < t) {
        float4 x0 = h4[g_csr[p].x * 32 + lane];
        acc.x += x0.x; acc.y += x0.y; acc.z += x0.z; acc.w += x0.w;
    }
    float id = g_invdeg[w];
    float4 hh = h4[w * 32 + lane];
    acc.x = hh.x + acc.x * id; acc.y = hh.y + acc.y * id;
    acc.z = hh.z + acc.z * id; acc.w = hh.w + acc.w * id;
    ((float4*)g_u32)[w * 32 + lane] = acc;
}

// g_h = relu( [u|v] @ [W;We] + c*t ) — fp16x2: A fp16, B fp16 hi+lo (exact B).
__global__ __launch_bounds__(256, 2) void k_gemm(int layer, int first_stage,
                                                 const float* __restrict__ tvec) {
    extern __shared__ char sm_[];
    __half* As    = (__half*)(sm_ + A_OFF);
    __half* Bs_hi = (__half*)(sm_ + B_HI_OFF);
    __half* Bs_lo = (__half*)(sm_ + B_LO_OFF);
    float* sb = (float*)(sm_ + SB_OFF);

    int tid = threadIdx.x;
    int warp = tid >> 5, l = tid & 31;
    if (tid < 128) sb[tid] = tvec ? tvec[tid] : g_t0[tid];
    int row0 = blockIdx.x * 128;
    int wm = (warp >> 1) * 32, wn = (warp & 1) * 64;

    const __half* Whi = g_Whi + layer * 32768;
    const __half* Wlo = g_Wlo + layer * 32768;

    int ar = tid >> 1, asc = (tid & 1) * 2;
    int bk = tid >> 3, bsc = (tid & 7) * 2;

    auto issue = [&](int s, int buf) {
        const __half* Af = (s < 4) ? g_uf : g_vf;
        int akb = (s & 3) * 32;
        int grow = row0 + ar; if (grow >= NN) grow = NN - 1;
        const __half* ap = Af + grow * 128 + akb + asc * 8;
        uint32_t da = sptr(As + (buf * 128 + ar) * 40 + asc * 8);
        CP16(da, ap); CP16(da + 16, ap + 8);
        const __half* bh = Whi + (s * 32 + bk) * 128 + bsc * 8;
        const __half* bl = Wlo + (s * 32 + bk) * 128 + bsc * 8;
        uint32_t eh = sptr(Bs_hi + (buf * 32 + bk) * 136 + bsc * 8);
        uint32_t el = sptr(Bs_lo + (buf * 32 + bk) * 136 + bsc * 8);
        CP16(eh, bh); CP16(eh + 16, bh + 8);
        CP16(el, bl); CP16(el + 16, bl + 8);
        CPCOMMIT();
    };

    float acc[2][8][4];
#pragma unroll
    for (int a = 0; a < 2; a++)
#pragma unroll
        for (int b = 0; b < 8; b++)
#pragma unroll
            for (int c = 0; c < 4; c++) acc[a][b][c] = 0.f;

    int rA = (l & 7) + ((l >> 3) & 1) * 8;
    int cA = (l >> 4) * 8;
    uint32_t aA0 = sptr(As + (wm + rA) * 40 + cA);
    uint32_t bHi0 = sptr(Bs_hi + rA * 136 + wn + cA);
    uint32_t bLo0 = sptr(Bs_lo + rA * 136 + wn + cA);

    issue(first_stage, 0);
#pragma unroll 1
    for (int s = first_stage; s < 8; s++) {
        int buf = (s - first_stage) & 1;
        if (s + 1 < 8) issue(s + 1, buf ^ 1);
        if (s + 1 < 8) { CPWAIT(1); } else { CPWAIT(0); }
        __syncthreads();

        uint32_t aA = aA0 + buf * ABUF;
        uint32_t bHi = bHi0 + buf * BBUF, bLo = bLo0 + buf * BBUF;
#pragma unroll
        for (int ks = 0; ks < 2; ks++) {
            int k16 = ks * 16;
            uint32_t ah[2][4];
#pragma unroll
            for (int mt = 0; mt < 2; mt++)
                LDSM4(ah[mt], aA + (mt * 16 * 40 + k16) * 2);
#pragma unroll
            for (int ng = 0; ng < 4; ng++) {
                uint32_t bh[4], bl[4];
                LDSM4T(bh, bHi + (k16 * 136 + ng * 16) * 2);
                LDSM4T(bl, bLo + (k16 * 136 + ng * 16) * 2);
#pragma unroll
                for (int mt = 0; mt < 2; mt++) {
#pragma unroll
                    for (int sub = 0; sub < 2; sub++) {
                        float* C = acc[mt][ng * 2 + sub];
                        MMA(C, ah[mt], &bh[sub * 2]);
                        MMA(C, ah[mt], &bl[sub * 2]);
                    }
                }
            }
        }
        __syncthreads();
    }

    int gq = l >> 2, tg = l & 3;
#pragma unroll
    for (int mt = 0; mt < 2; mt++) {
        int r1 = row0 + wm + mt * 16 + gq;
        int r2 = r1 + 8;
        float c1 = (r1 < NN) ? g_c[r1] : 0.f;
        float c2 = (r2 < NN) ? g_c[r2] : 0.f;
#pragma unroll
        for (int nt = 0; nt < 8; nt++) {
            int col = wn + nt * 8 + tg * 2;
            float b0 = sb[col], b1 = sb[col + 1];
            float* C = acc[mt][nt];
            float v0 = fmaxf(C[0] + c1 * b0, 0.f), v1 = fmaxf(C[1] + c1 * b1, 0.f);
            float v2 = fmaxf(C[2] + c2 * b0, 0.f), v3 = fmaxf(C[3] + c2 * b1, 0.f);
            if (r1 < NN) *(float2*)&g_h[r1 * 128 + col] = make_float2(v0, v1);
            if (r2 < NN) *(float2*)&g_h[r2 * 128 + col] = make_float2(v2, v3);
        }
    }
}

// ---------------- fused pool + collapsed last layer + classifier ------------
__device__ __forceinline__ int lower_bound(const int* a, int n, int key) {
    int lo = 0, hi = n;
    while (lo < hi) {
        int mid = (lo + hi) >> 1;
        if (a[mid] < key) lo = mid + 1; else hi = mid;
    }
    return lo;
}

__global__ void k_pool_out(const int* __restrict__ batch,
                           const float* __restrict__ bp,
                           float* __restrict__ out) {
    int g = blockIdx.x, t = threadIdx.x;
    __shared__ int s_lo, s_hi;
    __shared__ float sp[256];
    __shared__ float spc[256];
    if (t == 0) s_lo = lower_bound(batch, NN, g);
    if (t == 1) s_hi = lower_bound(batch, NN, g + 1);
    __syncthreads();
    int lo = s_lo, hi = s_hi;
    float sum = 0.f;
    if (t < 128) {
        for (int r = lo; r < hi; r++) sum += g_u32[r * 128 + t];
    } else {
        int q = t - 128;
        for (int r = lo; r < hi; r++)
            sum += __half2float(g_vf[r * 128 + q]);
    }
    float csum = 0.f;
    for (int r = lo + t; r < hi; r += 256) csum += g_c[r];
    float inv = 1.f / fmaxf((float)(hi - lo), 1.f);
    sp[t] = sum * inv;
    spc[t] = csum;
    __syncthreads();
#pragma unroll
    for (int s = 128; s > 0; s >>= 1) {
        if (t < s) spc[t] += spc[t + s];
        __syncthreads();
    }
    float pcm = spc[0] * inv;
    if (t < 128) {
        float acc = fmaf(pcm, g_bw[t], bp[t]);
#pragma unroll 8
        for (int k = 0; k < 256; k++) acc = fmaf(sp[k], g_Wcomb[k * 128 + t], acc);
        out[g * 128 + t] = acc;
    }
}

// ---------------- launch ----------------------------------------------------
extern "C" void kernel_launch(void* const* d_in, const int* in_sizes, int n_in,
                              void* d_out, int out_size) {
    const int*   ei    = (const int*)d_in[1];
    const float* ea    = (const float*)d_in[2];
    const int*   batch = (const int*)d_in[3];
    const float* emb   = (const float*)d_in[4];
    const float* Ws    = (const float*)d_in[5];
    const float* bs    = (const float*)d_in[6];
    const float* Wes   = (const float*)d_in[7];
    const float* Wp    = (const float*)d_in[8];
    const float* bp    = (const float*)d_in[9];
    float* out = (float*)d_out;

    static cudaStream_t sB = 0;
    static cudaEvent_t evFork = 0, evPrep = 0;
    static int initialized = 0;
    if (!initialized) {
        initialized = 1;
        cudaFuncSetAttribute(k_gemm, cudaFuncAttributeMaxDynamicSharedMemorySize,
                             GEMM_SMEM);
        bool ok = (cudaStreamCreateWithFlags(&sB, cudaStreamNonBlocking) == cudaSuccess) &&
                  (cudaEventCreateWithFlags(&evFork, cudaEventDisableTiming) == cudaSuccess) &&
                  (cudaEventCreateWithFlags(&evPrep, cudaEventDisableTiming) == cudaSuccess);
        if (!ok) sB = 0;
    }
    bool par = (sB != 0);

    // weight prep on side stream (independent of CSR chain)
    if (par) {
        cudaEventRecord(evFork, 0);
        cudaStreamWaitEvent(sB, evFork, 0);
        k_prep<<<642, 256, 0, sB>>>(Ws, Wes, bs, Wp, emb);
        cudaEventRecord(evPrep, sB);
    } else {
        k_prep<<<642, 256>>>(Ws, Wes, bs, Wp, emb);
    }

    // CSR chain + layers on the main stream, full-grid each
    k_zero<<<NBLK, 256>>>();
    k_count<<<(NE + 255) / 256, 256>>>(ei);
    k_scan1<<<NBLK, 256>>>();
    k_scan3z<<<NBLK, 256>>>();
    k_fill<<<(NE + 255) / 256, 256>>>(ei);
    k_v<<<GR_SPMM, 256>>>(ea);

    if (par) cudaStreamWaitEvent(0, evPrep, 0);   // weights/t0 ready
    // layer 0: rank-1 shortcut, K=128 (v@We0 only)
    k_gemm<<<NTILE, 256, GEMM_SMEM>>>(0, 4, nullptr);
    // layers 1..3
    for (int l = 1; l < 4; l++) {
        k_spmm_split<<<GR_SPMM, 256>>>();
        k_gemm<<<NTILE, 256, GEMM_SMEM>>>(l, 0, bs + l * 128);
    }
    // layer 4 collapsed into pooled path
    k_spmm_f32<<<GR_SPMM, 256>>>();
    k_pool_out<<<NG, 256>>>(batch, bp, out);
}